// round 1
// baseline (speedup 1.0000x reference)
#include <cuda_runtime.h>
#include <cuda_bf16.h>
#include <cstdint>

// ---------------------------------------------------------------------------
// CoMA forward: 3x (ChebConv K=6 -> ReLU -> Pool) -> Linear(25024,128) -> ReLU
//               -> Linear(128,2)
// Layout: all node features kept node-major (N, B*F) so graph gathers/scatters
// are contiguous per node.
// ---------------------------------------------------------------------------

#define BATCH 32
#define KORD 6

static const int N0 = 50000, N1 = 12500, N2 = 3125, N3 = 782;
static const int E0 = 300000, E1 = 75000, E2 = 18750;

// one big scratch pool: 7 slots of 6.4M floats + enc accumulator
#define SLOT 6400000
__device__ float g_buf[7 * SLOT + 4096];

// ---------------------------------------------------------------------------
// transpose x (B, N, 3) -> xt (N, B*3)
__global__ void k_transpose(const float* __restrict__ x, float* __restrict__ xt, int N)
{
    int idx = blockIdx.x * blockDim.x + threadIdx.x;
    int total = BATCH * N * 3;
    if (idx >= total) return;
    int c = idx % 3;
    int n = (idx / 3) % N;
    int b = idx / (3 * N);
    xt[(size_t)n * (BATCH * 3) + b * 3 + c] = x[idx];
}

__global__ void k_zero4(float4* p, int n4)
{
    int i = blockIdx.x * blockDim.x + threadIdx.x;
    if (i < n4) p[i] = make_float4(0.f, 0.f, 0.f, 0.f);
}

__global__ void k_copyneg4(float4* __restrict__ d, const float4* __restrict__ s, int n4)
{
    int i = blockIdx.x * blockDim.x + threadIdx.x;
    if (i < n4) {
        float4 v = s[i];
        d[i] = make_float4(-v.x, -v.y, -v.z, -v.w);
    }
}

// ---------------------------------------------------------------------------
// propagate: dst[row] += scale * norm[e] * src[col]   (W4 float4 chunks/node)
template <int W4>
__global__ void k_prop(const int* __restrict__ rows, const int* __restrict__ cols,
                       const float* __restrict__ norm, float scale,
                       const float* __restrict__ src, float* __restrict__ dst, int E)
{
    int idx = blockIdx.x * blockDim.x + threadIdx.x;
    int total = E * W4;
    if (idx >= total) return;
    int e  = idx / W4;
    int c4 = idx - e * W4;
    float nv = norm[e] * scale;
    int cs = cols[e];
    int rd = rows[e];
    float4 v = ((const float4*)src)[(size_t)cs * W4 + c4];
    float4* d = ((float4*)dst) + (size_t)rd * W4 + c4;
    asm volatile("red.global.add.v4.f32 [%0], {%1,%2,%3,%4};"
                 :: "l"(d), "f"(v.x * nv), "f"(v.y * nv), "f"(v.z * nv), "f"(v.w * nv)
                 : "memory");
}

// ---------------------------------------------------------------------------
// fused: for each pooled output row r:
//   out[r] = sum_{j=0..2} pval * relu( bias + sum_k T_k[col_j] @ w_k )
struct TPtrs { const float* T[KORD]; };

template <int FIN, int FOUT>
__global__ void k_pool_cheb(TPtrs tp, const float* __restrict__ w,
                            const float* __restrict__ bias,
                            const int* __restrict__ pcols,
                            const float* __restrict__ pvals,
                            float* __restrict__ out, int n_out)
{
    constexpr int FINP = (FIN % 2 == 0) ? FIN + 1 : FIN;   // bank-conflict pad
    constexpr int NO   = FOUT / 4;                          // outputs per thread

    __shared__ __align__(16) float sW[KORD * FIN * FOUT];
    __shared__ float sT[KORD][32 * FINP];

    int tid = threadIdx.x;
    for (int i = tid; i < KORD * FIN * FOUT; i += 128) sW[i] = w[i];

    int b  = tid & 31;
    int og = tid >> 5;      // 0..3

    float bz[NO], acc[NO];
#pragma unroll
    for (int j = 0; j < NO; j++) { bz[j] = bias[og * NO + j]; acc[j] = 0.f; }

    int r = blockIdx.x;
    if (r >= n_out) return;

#pragma unroll
    for (int j3 = 0; j3 < 3; j3++) {
        int   col = pcols[r * 3 + j3];
        float pv  = pvals[r * 3 + j3];
        __syncthreads();
#pragma unroll
        for (int k = 0; k < KORD; k++) {
            const float* src = tp.T[k] + (size_t)col * (32 * FIN);
            for (int i = tid; i < 32 * FIN; i += 128) {
                int bb = i / FIN, ii = i - bb * FIN;
                sT[k][bb * FINP + ii] = src[i];
            }
        }
        __syncthreads();

        float y[NO];
#pragma unroll
        for (int j = 0; j < NO; j++) y[j] = bz[j];

#pragma unroll
        for (int k = 0; k < KORD; k++) {
            float rT[FIN];
#pragma unroll
            for (int i = 0; i < FIN; i++) rT[i] = sT[k][b * FINP + i];
#pragma unroll
            for (int i = 0; i < FIN; i++) {
                const float* wrow = &sW[(k * FIN + i) * FOUT + og * NO];
#pragma unroll
                for (int j = 0; j < NO; j += 4) {
                    float4 w4 = *(const float4*)(wrow + j);
                    y[j + 0] += rT[i] * w4.x;
                    y[j + 1] += rT[i] * w4.y;
                    y[j + 2] += rT[i] * w4.z;
                    y[j + 3] += rT[i] * w4.w;
                }
            }
        }
#pragma unroll
        for (int j = 0; j < NO; j++) acc[j] += pv * fmaxf(y[j], 0.f);
    }

    float* o = out + ((size_t)r * 32 + b) * FOUT + og * NO;
#pragma unroll
    for (int j = 0; j < NO; j++) o[j] = acc[j];
}

// ---------------------------------------------------------------------------
// encoder split-K GEMM: enc[b,z] += sum_{n,f} h[n,b,f] * wenc[(n*32+f)*128+z]
__global__ void k_enc(const float* __restrict__ h, const float* __restrict__ wenc,
                      float* __restrict__ enc, int N)
{
    __shared__ float sH[8 * 32 * 32];
    int tid = threadIdx.x;
    int n0  = blockIdx.x * 8;
    int nn  = min(8, N - n0);
    for (int i = tid; i < nn * 1024; i += 256) sH[i] = h[(size_t)n0 * 1024 + i];
    __syncthreads();

    int z  = tid & 127;
    int bh = tid >> 7;   // 0..1
    float acc[16];
#pragma unroll
    for (int j = 0; j < 16; j++) acc[j] = 0.f;

    for (int n = 0; n < nn; n++) {
#pragma unroll
        for (int f = 0; f < 32; f++) {
            float wv = wenc[((size_t)(n0 + n) * 32 + f) * 128 + z];
#pragma unroll
            for (int j = 0; j < 16; j++)
                acc[j] += wv * sH[n * 1024 + (bh * 16 + j) * 32 + f];
        }
    }
#pragma unroll
    for (int j = 0; j < 16; j++)
        atomicAdd(&enc[(bh * 16 + j) * 128 + z], acc[j]);
}

__global__ void k_final(const float* __restrict__ enc, const float* __restrict__ benc,
                        const float* __restrict__ wcls, const float* __restrict__ bcls,
                        float* __restrict__ out)
{
    int t = threadIdx.x;
    if (t >= 64) return;
    int b = t >> 1, c = t & 1;
    float a = bcls[c];
    for (int z = 0; z < 128; z++) {
        float e = fmaxf(enc[b * 128 + z] + benc[z], 0.f);
        a += e * wcls[z * 2 + c];
    }
    out[b * 2 + c] = a;
}

// ---------------------------------------------------------------------------
template <int FIN>
static void run_cheb(const float* T0, float* Tk1, float* Tk2, float* Tk3,
                     float* Tk4, float* Tk5, int N, int E,
                     const int* edge, const float* norm)
{
    constexpr int W4 = (32 * FIN) / 4;
    float* Ts[6] = {(float*)T0, Tk1, Tk2, Tk3, Tk4, Tk5};
    int n4  = N * W4;
    int tot = E * W4;
    int gN  = (n4 + 255) / 256;
    int gE  = (tot + 255) / 256;

    k_zero4<<<gN, 256>>>((float4*)Ts[1], n4);
    k_prop<W4><<<gE, 256>>>(edge, edge + E, norm, 1.f, Ts[0], Ts[1], E);
    for (int k = 2; k < KORD; k++) {
        k_copyneg4<<<gN, 256>>>((float4*)Ts[k], (const float4*)Ts[k - 2], n4);
        k_prop<W4><<<gE, 256>>>(edge, edge + E, norm, 2.f, Ts[k - 1], Ts[k], E);
    }
}

extern "C" void kernel_launch(void* const* d_in, const int* in_sizes, int n_in,
                              void* d_out, int out_size)
{
    const float* x;
    const int*   edge[3];
    const float* norm[3];
    const int*   pidx[3];
    const float* pval[3];
    const float *w[3], *bb[3], *wenc, *benc, *wcls, *bcls;

    if (in_sizes[3] == 150000) {
        // reference-signature order: x, e0,n0, e1,n1, e2,n2, p0,v0, p1,v1, p2,v2, ...
        x = (const float*)d_in[0];
        edge[0] = (const int*)d_in[1];  norm[0] = (const float*)d_in[2];
        edge[1] = (const int*)d_in[3];  norm[1] = (const float*)d_in[4];
        edge[2] = (const int*)d_in[5];  norm[2] = (const float*)d_in[6];
        pidx[0] = (const int*)d_in[7];  pval[0] = (const float*)d_in[8];
        pidx[1] = (const int*)d_in[9];  pval[1] = (const float*)d_in[10];
        pidx[2] = (const int*)d_in[11]; pval[2] = (const float*)d_in[12];
    } else {
        // setup_inputs dict order: x, (e,n,p,v) x3, ...
        x = (const float*)d_in[0];
        edge[0] = (const int*)d_in[1];  norm[0] = (const float*)d_in[2];
        pidx[0] = (const int*)d_in[3];  pval[0] = (const float*)d_in[4];
        edge[1] = (const int*)d_in[5];  norm[1] = (const float*)d_in[6];
        pidx[1] = (const int*)d_in[7];  pval[1] = (const float*)d_in[8];
        edge[2] = (const int*)d_in[9];  norm[2] = (const float*)d_in[10];
        pidx[2] = (const int*)d_in[11]; pval[2] = (const float*)d_in[12];
    }
    w[0]  = (const float*)d_in[13]; bb[0] = (const float*)d_in[14];
    w[1]  = (const float*)d_in[15]; bb[1] = (const float*)d_in[16];
    w[2]  = (const float*)d_in[17]; bb[2] = (const float*)d_in[18];
    wenc  = (const float*)d_in[19]; benc  = (const float*)d_in[20];
    wcls  = (const float*)d_in[21]; bcls  = (const float*)d_in[22];

    float* base = nullptr;
    cudaGetSymbolAddress((void**)&base, g_buf);
    float* H0 = base;
    float* H1 = base + (size_t)SLOT;
    float* T1 = base + (size_t)2 * SLOT;
    float* T2 = base + (size_t)3 * SLOT;
    float* T3 = base + (size_t)4 * SLOT;
    float* T4 = base + (size_t)5 * SLOT;
    float* T5 = base + (size_t)6 * SLOT;
    float* enc = base + (size_t)7 * SLOT;

    // ---- layer 0: N0, Fin=3, Fout=16 ----
    {
        int total = BATCH * N0 * 3;
        k_transpose<<<(total + 255) / 256, 256>>>(x, H0, N0);
        run_cheb<3>(H0, T1, T2, T3, T4, T5, N0, E0, edge[0], norm[0]);
        TPtrs tp; tp.T[0] = H0; tp.T[1] = T1; tp.T[2] = T2; tp.T[3] = T3; tp.T[4] = T4; tp.T[5] = T5;
        k_pool_cheb<3, 16><<<N1, 128>>>(tp, w[0], bb[0],
                                        pidx[0] + (size_t)N1 * 3, pval[0], H1, N1);
    }
    // ---- layer 1: N1, Fin=16, Fout=16 ----
    {
        run_cheb<16>(H1, T1, T2, T3, T4, T5, N1, E1, edge[1], norm[1]);
        TPtrs tp; tp.T[0] = H1; tp.T[1] = T1; tp.T[2] = T2; tp.T[3] = T3; tp.T[4] = T4; tp.T[5] = T5;
        k_pool_cheb<16, 16><<<N2, 128>>>(tp, w[1], bb[1],
                                         pidx[1] + (size_t)N2 * 3, pval[1], H0, N2);
    }
    // ---- layer 2: N2, Fin=16, Fout=32 ----
    {
        run_cheb<16>(H0, T1, T2, T3, T4, T5, N2, E2, edge[2], norm[2]);
        TPtrs tp; tp.T[0] = H0; tp.T[1] = T1; tp.T[2] = T2; tp.T[3] = T3; tp.T[4] = T4; tp.T[5] = T5;
        k_pool_cheb<16, 32><<<N3, 128>>>(tp, w[2], bb[2],
                                         pidx[2] + (size_t)N3 * 3, pval[2], H1, N3);
    }
    // ---- encoder + classifier ----
    k_zero4<<<4, 256>>>((float4*)enc, 1024);
    k_enc<<<(N3 + 7) / 8, 256>>>(H1, wenc, enc, N3);
    k_final<<<1, 64>>>(enc, benc, wcls, bcls, (float*)d_out);
}

// round 2
// speedup vs baseline: 1.3937x; 1.3937x over previous
#include <cuda_runtime.h>
#include <cuda_bf16.h>
#include <cstdint>

// ---------------------------------------------------------------------------
// CoMA forward: 3x (ChebConv K=6 -> ReLU -> Pool) -> Linear(25024,128) -> ReLU
//               -> Linear(128,2)
// Node-major layout (N, B*F). Chebyshev propagation done GATHER-style via a
// per-call fixed-stride CSR bucket build (no atomics in the hot path, and the
// -T_{k-2} term is fused into the gather, eliminating all init kernels).
// ---------------------------------------------------------------------------

#define BATCH 32
#define KORD 6
#define CAP 64   // max in-degree bucket capacity (Poisson(6): P(>=64) ~ 0)

static const int N0 = 50000, N1 = 12500, N2 = 3125, N3 = 782;
static const int E0 = 300000, E1 = 75000, E2 = 18750;

// scratch pool: 7 slots of 6.4M floats + enc accumulator
#define SLOT 6400000
__device__ __align__(16) float g_buf[7 * SLOT + 4096];
// CSR buckets (sized for layer 0)
__device__ int   g_bcol[(size_t)50000 * CAP];
__device__ float g_bval[(size_t)50000 * CAP];
__device__ int   g_deg[50000];

// ---------------------------------------------------------------------------
// transpose x (B, N, 3) -> xt (N, B*3)
__global__ void k_transpose(const float* __restrict__ x, float* __restrict__ xt, int N)
{
    int idx = blockIdx.x * blockDim.x + threadIdx.x;
    int total = BATCH * N * 3;
    if (idx >= total) return;
    int c = idx % 3;
    int n = (idx / 3) % N;
    int b = idx / (3 * N);
    xt[(size_t)n * (BATCH * 3) + b * 3 + c] = x[idx];
}

__global__ void k_zero4(float4* p, int n4)
{
    int i = blockIdx.x * blockDim.x + threadIdx.x;
    if (i < n4) p[i] = make_float4(0.f, 0.f, 0.f, 0.f);
}

__global__ void k_zero_deg(int n)
{
    int i = blockIdx.x * blockDim.x + threadIdx.x;
    if (i < n) g_deg[i] = 0;
}

// build fixed-stride incoming-edge buckets: for edge e, append (col, norm) to
// bucket of row.
__global__ void k_bucket(const int* __restrict__ rows, const int* __restrict__ cols,
                         const float* __restrict__ norm, int E)
{
    int e = blockIdx.x * blockDim.x + threadIdx.x;
    if (e >= E) return;
    int r = rows[e];
    int d = atomicAdd(&g_deg[r], 1);
    if (d < CAP) {
        g_bcol[(size_t)r * CAP + d] = cols[e];
        g_bval[(size_t)r * CAP + d] = norm[e];
    }
}

// ---------------------------------------------------------------------------
// gather propagate:
//   dst[n] = (prev ? -prev[n] : 0) + scale * sum_{j in bucket(n)} norm_j * src[col_j]
// LPN lanes cooperate per node; each lane owns float4 chunk c4 (< W4).
template <int W4, int LPN>
__global__ void k_prop_g(const float* __restrict__ prev,
                         const float* __restrict__ src,
                         float* __restrict__ dst,
                         float scale, int N)
{
    int tid  = threadIdx.x;
    int node = blockIdx.x * (256 / LPN) + tid / LPN;
    int c4   = tid % LPN;
    if (node >= N) return;
    if (LPN > W4 && c4 >= W4) return;

    int d = min(g_deg[node], CAP);
    const int*   bc = g_bcol + (size_t)node * CAP;
    const float* bv = g_bval + (size_t)node * CAP;

    float4 acc;
    if (prev) {
        float4 p = ((const float4*)prev)[(size_t)node * W4 + c4];
        acc = make_float4(-p.x, -p.y, -p.z, -p.w);
    } else {
        acc = make_float4(0.f, 0.f, 0.f, 0.f);
    }

    const float4* s4 = (const float4*)src;
    int j = 0;
    // software pipeline by 2 to expose MLP
    for (; j + 2 <= d; j += 2) {
        int   c0 = bc[j],     c1 = bc[j + 1];
        float v0 = bv[j] * scale, v1 = bv[j + 1] * scale;
        float4 a = s4[(size_t)c0 * W4 + c4];
        float4 b = s4[(size_t)c1 * W4 + c4];
        acc.x += v0 * a.x + v1 * b.x;
        acc.y += v0 * a.y + v1 * b.y;
        acc.z += v0 * a.z + v1 * b.z;
        acc.w += v0 * a.w + v1 * b.w;
    }
    if (j < d) {
        int   c0 = bc[j];
        float v0 = bv[j] * scale;
        float4 a = s4[(size_t)c0 * W4 + c4];
        acc.x += v0 * a.x; acc.y += v0 * a.y;
        acc.z += v0 * a.z; acc.w += v0 * a.w;
    }
    ((float4*)dst)[(size_t)node * W4 + c4] = acc;
}

// ---------------------------------------------------------------------------
// fused: for each pooled output row r:
//   out[r] = sum_{j=0..2} pval * relu( bias + sum_k T_k[col_j] @ w_k )
struct TPtrs { const float* T[KORD]; };

template <int FIN, int FOUT>
__global__ void k_pool_cheb(TPtrs tp, const float* __restrict__ w,
                            const float* __restrict__ bias,
                            const int* __restrict__ pcols,
                            const float* __restrict__ pvals,
                            float* __restrict__ out, int n_out)
{
    constexpr int FINP = (FIN % 2 == 0) ? FIN + 1 : FIN;   // bank-conflict pad
    constexpr int NO   = FOUT / 4;                          // outputs per thread

    __shared__ __align__(16) float sW[KORD * FIN * FOUT];
    __shared__ float sT[KORD][32 * FINP];

    int tid = threadIdx.x;
    for (int i = tid; i < KORD * FIN * FOUT; i += 128) sW[i] = w[i];

    int b  = tid & 31;
    int og = tid >> 5;      // 0..3

    float bz[NO], acc[NO];
#pragma unroll
    for (int j = 0; j < NO; j++) { bz[j] = bias[og * NO + j]; acc[j] = 0.f; }

    int r = blockIdx.x;
    if (r >= n_out) return;

#pragma unroll
    for (int j3 = 0; j3 < 3; j3++) {
        int   col = pcols[r * 3 + j3];
        float pv  = pvals[r * 3 + j3];
        __syncthreads();
#pragma unroll
        for (int k = 0; k < KORD; k++) {
            const float* src = tp.T[k] + (size_t)col * (32 * FIN);
            for (int i = tid; i < 32 * FIN; i += 128) {
                int bb = i / FIN, ii = i - bb * FIN;
                sT[k][bb * FINP + ii] = src[i];
            }
        }
        __syncthreads();

        float y[NO];
#pragma unroll
        for (int j = 0; j < NO; j++) y[j] = bz[j];

#pragma unroll
        for (int k = 0; k < KORD; k++) {
            float rT[FIN];
#pragma unroll
            for (int i = 0; i < FIN; i++) rT[i] = sT[k][b * FINP + i];
#pragma unroll
            for (int i = 0; i < FIN; i++) {
                const float* wrow = &sW[(k * FIN + i) * FOUT + og * NO];
#pragma unroll
                for (int j = 0; j < NO; j += 4) {
                    float4 w4 = *(const float4*)(wrow + j);
                    y[j + 0] += rT[i] * w4.x;
                    y[j + 1] += rT[i] * w4.y;
                    y[j + 2] += rT[i] * w4.z;
                    y[j + 3] += rT[i] * w4.w;
                }
            }
        }
#pragma unroll
        for (int j = 0; j < NO; j++) acc[j] += pv * fmaxf(y[j], 0.f);
    }

    float* o = out + ((size_t)r * 32 + b) * FOUT + og * NO;
#pragma unroll
    for (int j = 0; j < NO; j++) o[j] = acc[j];
}

// ---------------------------------------------------------------------------
// encoder split-K GEMM: enc[b,z] += sum_{n,f} h[n,b,f] * wenc[(n*32+f)*128+z]
__global__ void k_enc(const float* __restrict__ h, const float* __restrict__ wenc,
                      float* __restrict__ enc, int N)
{
    __shared__ float sH[8 * 32 * 32];
    int tid = threadIdx.x;
    int n0  = blockIdx.x * 8;
    int nn  = min(8, N - n0);
    for (int i = tid; i < nn * 1024; i += 256) sH[i] = h[(size_t)n0 * 1024 + i];
    __syncthreads();

    int z  = tid & 127;
    int bh = tid >> 7;   // 0..1
    float acc[16];
#pragma unroll
    for (int j = 0; j < 16; j++) acc[j] = 0.f;

    for (int n = 0; n < nn; n++) {
#pragma unroll
        for (int f = 0; f < 32; f++) {
            float wv = wenc[((size_t)(n0 + n) * 32 + f) * 128 + z];
#pragma unroll
            for (int j = 0; j < 16; j++)
                acc[j] += wv * sH[n * 1024 + (bh * 16 + j) * 32 + f];
        }
    }
#pragma unroll
    for (int j = 0; j < 16; j++)
        atomicAdd(&enc[(bh * 16 + j) * 128 + z], acc[j]);
}

__global__ void k_final(const float* __restrict__ enc, const float* __restrict__ benc,
                        const float* __restrict__ wcls, const float* __restrict__ bcls,
                        float* __restrict__ out)
{
    int t = threadIdx.x;
    if (t >= 64) return;
    int b = t >> 1, c = t & 1;
    float a = bcls[c];
    for (int z = 0; z < 128; z++) {
        float e = fmaxf(enc[b * 128 + z] + benc[z], 0.f);
        a += e * wcls[z * 2 + c];
    }
    out[b * 2 + c] = a;
}

// ---------------------------------------------------------------------------
template <int FIN, int LPN>
static void run_cheb_g(float* Ts[6], int N, int E,
                       const int* edge, const float* norm)
{
    constexpr int W4  = (32 * FIN) / 4;
    constexpr int NPB = 256 / LPN;       // nodes per block
    int gN = (N + NPB - 1) / NPB;

    // build buckets
    k_zero_deg<<<(N + 255) / 256, 256>>>(N);
    k_bucket<<<(E + 255) / 256, 256>>>(edge, edge + E, norm, E);

    // T1 = L @ T0
    k_prop_g<W4, LPN><<<gN, 256>>>(nullptr, Ts[0], Ts[1], 1.f, N);
    // Tk = 2 L T_{k-1} - T_{k-2}
    for (int k = 2; k < KORD; k++)
        k_prop_g<W4, LPN><<<gN, 256>>>(Ts[k - 2], Ts[k - 1], Ts[k], 2.f, N);
}

extern "C" void kernel_launch(void* const* d_in, const int* in_sizes, int n_in,
                              void* d_out, int out_size)
{
    const float* x;
    const int*   edge[3];
    const float* norm[3];
    const int*   pidx[3];
    const float* pval[3];
    const float *w[3], *bb[3], *wenc, *benc, *wcls, *bcls;

    if (in_sizes[3] == 150000) {
        // reference-signature order
        x = (const float*)d_in[0];
        edge[0] = (const int*)d_in[1];  norm[0] = (const float*)d_in[2];
        edge[1] = (const int*)d_in[3];  norm[1] = (const float*)d_in[4];
        edge[2] = (const int*)d_in[5];  norm[2] = (const float*)d_in[6];
        pidx[0] = (const int*)d_in[7];  pval[0] = (const float*)d_in[8];
        pidx[1] = (const int*)d_in[9];  pval[1] = (const float*)d_in[10];
        pidx[2] = (const int*)d_in[11]; pval[2] = (const float*)d_in[12];
    } else {
        // setup_inputs dict order
        x = (const float*)d_in[0];
        edge[0] = (const int*)d_in[1];  norm[0] = (const float*)d_in[2];
        pidx[0] = (const int*)d_in[3];  pval[0] = (const float*)d_in[4];
        edge[1] = (const int*)d_in[5];  norm[1] = (const float*)d_in[6];
        pidx[1] = (const int*)d_in[7];  pval[1] = (const float*)d_in[8];
        edge[2] = (const int*)d_in[9];  norm[2] = (const float*)d_in[10];
        pidx[2] = (const int*)d_in[11]; pval[2] = (const float*)d_in[12];
    }
    w[0]  = (const float*)d_in[13]; bb[0] = (const float*)d_in[14];
    w[1]  = (const float*)d_in[15]; bb[1] = (const float*)d_in[16];
    w[2]  = (const float*)d_in[17]; bb[2] = (const float*)d_in[18];
    wenc  = (const float*)d_in[19]; benc  = (const float*)d_in[20];
    wcls  = (const float*)d_in[21]; bcls  = (const float*)d_in[22];

    float* base = nullptr;
    cudaGetSymbolAddress((void**)&base, g_buf);
    float* H0 = base;
    float* H1 = base + (size_t)SLOT;
    float* T1 = base + (size_t)2 * SLOT;
    float* T2 = base + (size_t)3 * SLOT;
    float* T3 = base + (size_t)4 * SLOT;
    float* T4 = base + (size_t)5 * SLOT;
    float* T5 = base + (size_t)6 * SLOT;
    float* enc = base + (size_t)7 * SLOT;

    // ---- layer 0: N0, Fin=3, Fout=16 ----
    {
        int total = BATCH * N0 * 3;
        k_transpose<<<(total + 255) / 256, 256>>>(x, H0, N0);
        float* Ts[6] = {H0, T1, T2, T3, T4, T5};
        run_cheb_g<3, 32>(Ts, N0, E0, edge[0], norm[0]);
        TPtrs tp; tp.T[0] = H0; tp.T[1] = T1; tp.T[2] = T2; tp.T[3] = T3; tp.T[4] = T4; tp.T[5] = T5;
        k_pool_cheb<3, 16><<<N1, 128>>>(tp, w[0], bb[0],
                                        pidx[0] + (size_t)N1 * 3, pval[0], H1, N1);
    }
    // ---- layer 1: N1, Fin=16, Fout=16 ----
    {
        float* Ts[6] = {H1, T1, T2, T3, T4, T5};
        run_cheb_g<16, 128>(Ts, N1, E1, edge[1], norm[1]);
        TPtrs tp; tp.T[0] = H1; tp.T[1] = T1; tp.T[2] = T2; tp.T[3] = T3; tp.T[4] = T4; tp.T[5] = T5;
        k_pool_cheb<16, 16><<<N2, 128>>>(tp, w[1], bb[1],
                                         pidx[1] + (size_t)N2 * 3, pval[1], H0, N2);
    }
    // ---- layer 2: N2, Fin=16, Fout=32 ----
    {
        float* Ts[6] = {H0, T1, T2, T3, T4, T5};
        run_cheb_g<16, 128>(Ts, N2, E2, edge[2], norm[2]);
        TPtrs tp; tp.T[0] = H0; tp.T[1] = T1; tp.T[2] = T2; tp.T[3] = T3; tp.T[4] = T4; tp.T[5] = T5;
        k_pool_cheb<16, 32><<<N3, 128>>>(tp, w[2], bb[2],
                                         pidx[2] + (size_t)N3 * 3, pval[2], H1, N3);
    }
    // ---- encoder + classifier ----
    k_zero4<<<4, 256>>>((float4*)enc, 1024);
    k_enc<<<(N3 + 7) / 8, 256>>>(H1, wenc, enc, N3);
    k_final<<<1, 64>>>(enc, benc, wcls, bcls, (float*)d_out);
}